// round 1
// baseline (speedup 1.0000x reference)
#include <cuda_runtime.h>
#include <math.h>

#define BB 8
#define NQ 2048
#define NK 2048
#define DD 256

// Scratch (static device allocations are allowed)
__device__ float g_cos[2048];
__device__ float g_kproj[BB * NK * DD];
__device__ float g_qproj[BB * NQ * DD];
__device__ float g_qfft [BB * NQ * DD];

// ---------------------------------------------------------------------------
// cos table: cos(2*pi*i/2048) = cospi(i/1024)
// ---------------------------------------------------------------------------
__global__ void cos_init_kernel() {
    int i = blockIdx.x * blockDim.x + threadIdx.x;
    if (i < 2048) g_cos[i] = cospif((float)i / 1024.0f);
}

// ---------------------------------------------------------------------------
// y[m,d] = sum_e x[m,e] * W[d,e] (+ bias[d])   M=16384, 256x256
// block: 64m x 64d, threads 256 (16x16), 4x4 per thread
// ---------------------------------------------------------------------------
__global__ void proj_kernel(const float* __restrict__ x,
                            const float* __restrict__ W,
                            const float* __restrict__ bias,
                            float* __restrict__ y,
                            int useBias) {
    __shared__ float xs[16][65];
    __shared__ float ws[16][65];
    int tid = threadIdx.x;
    int tx = tid & 15, ty = tid >> 4;
    int m0 = blockIdx.y * 64;
    int d0 = blockIdx.x * 64;
    float acc[4][4] = {};
    for (int e0 = 0; e0 < DD; e0 += 16) {
        __syncthreads();
        for (int i = tid; i < 1024; i += 256) {
            int ee = i & 15, mm = i >> 4;
            xs[ee][mm] = x[(m0 + mm) * DD + e0 + ee];
            ws[ee][mm] = W[(d0 + mm) * DD + e0 + ee];
        }
        __syncthreads();
#pragma unroll
        for (int ee = 0; ee < 16; ee++) {
            float a[4], b[4];
#pragma unroll
            for (int i = 0; i < 4; i++) a[i] = xs[ee][ty * 4 + i];
#pragma unroll
            for (int j = 0; j < 4; j++) b[j] = ws[ee][tx * 4 + j];
#pragma unroll
            for (int i = 0; i < 4; i++)
#pragma unroll
                for (int j = 0; j < 4; j++) acc[i][j] += a[i] * b[j];
        }
    }
#pragma unroll
    for (int i = 0; i < 4; i++) {
        int m = m0 + ty * 4 + i;
#pragma unroll
        for (int j = 0; j < 4; j++) {
            int d = d0 + tx * 4 + j;
            float v = acc[i][j];
            if (useBias) v += bias[d];
            y[m * DD + d] = v;
        }
    }
}

// ---------------------------------------------------------------------------
// qfft[b,k,d] = sum_n cos(2*pi*k*n/2048) * qproj[b,n,d] + bq[d]
// Cos matrix generated on the fly from 2048-entry smem table with an
// incremental index (idx += k mod 2048). block: 64k x 64d per batch.
// ---------------------------------------------------------------------------
__global__ void fft_kernel(const float* __restrict__ bq) {
    __shared__ float cosS[2048];
    __shared__ float qS[16][65];
    int tid = threadIdx.x;
    int tx = tid & 15, ty = tid >> 4;
    int d0 = blockIdx.x * 64;
    int k0 = blockIdx.y * 64;
    int b  = blockIdx.z;

    for (int i = tid; i < 2048; i += 256) cosS[i] = g_cos[i];

    int kq[4], idx[4];
#pragma unroll
    for (int i = 0; i < 4; i++) { kq[i] = k0 + ty * 4 + i; idx[i] = 0; }

    float acc[4][4] = {};
    const float* qp = g_qproj + (size_t)b * NQ * DD;
    __syncthreads();

    for (int n0 = 0; n0 < NQ; n0 += 16) {
        for (int i = tid; i < 1024; i += 256) {
            int dd = i & 63, nn = i >> 6;
            qS[nn][dd] = qp[(n0 + nn) * DD + d0 + dd];
        }
        __syncthreads();
#pragma unroll
        for (int nn = 0; nn < 16; nn++) {
            float a[4], bb[4];
#pragma unroll
            for (int i = 0; i < 4; i++) {
                a[i] = cosS[idx[i]];
                idx[i] = (idx[i] + kq[i]) & 2047;
            }
#pragma unroll
            for (int j = 0; j < 4; j++) bb[j] = qS[nn][tx * 4 + j];
#pragma unroll
            for (int i = 0; i < 4; i++)
#pragma unroll
                for (int j = 0; j < 4; j++) acc[i][j] += a[i] * bb[j];
        }
        __syncthreads();
    }
#pragma unroll
    for (int i = 0; i < 4; i++) {
#pragma unroll
        for (int j = 0; j < 4; j++) {
            int d = d0 + tx * 4 + j;
            g_qfft[((size_t)b * NQ + kq[i]) * DD + d] = acc[i][j] + bq[d];
        }
    }
}

// ---------------------------------------------------------------------------
// Flash attention: per (b, 64-row q tile). scores = qfft @ kproj^T / 16,
// online softmax, out += P @ V with V = original key.
// Dynamic smem layout (floats):
//   qS [16*65] | kS [16*65] | sS [64*65] | vS [64*256] | mS[64] lS[64] cS[64]
// ---------------------------------------------------------------------------
#define FL_QS   0
#define FL_KS   (16 * 65)
#define FL_SS   (2 * 16 * 65)
#define FL_VS   (FL_SS + 64 * 65)
#define FL_M    (FL_VS + 64 * 256)
#define FL_L    (FL_M + 64)
#define FL_C    (FL_L + 64)
#define FL_SMEM_FLOATS (FL_C + 64)

__global__ void flash_kernel(const float* __restrict__ keyv,
                             float* __restrict__ out) {
    extern __shared__ float sm[];
    float* qS = sm + FL_QS;   // [16][65]
    float* kS = sm + FL_KS;   // [16][65]
    float* sS = sm + FL_SS;   // [64][65]
    float* vS = sm + FL_VS;   // [64][256]
    float* mS = sm + FL_M;
    float* lS = sm + FL_L;
    float* cS = sm + FL_C;

    int tid = threadIdx.x;
    int tx = tid & 15, ty = tid >> 4;
    int q0 = blockIdx.x * 64;
    int b  = blockIdx.y;

    const float* qbase = g_qfft  + (size_t)b * NQ * DD;
    const float* kbase = g_kproj + (size_t)b * NK * DD;
    const float* vbase = keyv    + (size_t)b * NK * DD;

    if (tid < 64) { mS[tid] = -INFINITY; lS[tid] = 0.0f; }

    float oacc[4][16] = {};
    const float scale = 0.0625f;  // 1/sqrt(256)

    for (int kt = 0; kt < NK; kt += 64) {
        // ---- S = Q @ K^T ----
        float sacc[4][4] = {};
        for (int e0 = 0; e0 < DD; e0 += 16) {
            __syncthreads();
            for (int i = tid; i < 1024; i += 256) {
                int ee = i & 15, mm = i >> 4;
                qS[ee * 65 + mm] = qbase[(q0 + mm) * DD + e0 + ee];
                kS[ee * 65 + mm] = kbase[(kt + mm) * DD + e0 + ee];
            }
            __syncthreads();
#pragma unroll
            for (int ee = 0; ee < 16; ee++) {
                float a[4], bb[4];
#pragma unroll
                for (int i = 0; i < 4; i++) a[i] = qS[ee * 65 + ty * 4 + i];
#pragma unroll
                for (int j = 0; j < 4; j++) bb[j] = kS[ee * 65 + tx * 4 + j];
#pragma unroll
                for (int i = 0; i < 4; i++)
#pragma unroll
                    for (int j = 0; j < 4; j++) sacc[i][j] += a[i] * bb[j];
            }
        }

        // ---- stage S (scaled) and V tile ----
#pragma unroll
        for (int i = 0; i < 4; i++)
#pragma unroll
            for (int j = 0; j < 4; j++)
                sS[(ty * 4 + i) * 65 + tx * 4 + j] = sacc[i][j] * scale;
        const float* vsrc = vbase + (size_t)kt * DD;  // 64x256 contiguous
        for (int i = tid; i < 64 * 256; i += 256) vS[i] = vsrc[i];
        __syncthreads();

        // ---- online softmax (one thread per q row) ----
        if (tid < 64) {
            int r = tid;
            float mx = mS[r];
#pragma unroll 8
            for (int c = 0; c < 64; c++) mx = fmaxf(mx, sS[r * 65 + c]);
            float corr = __expf(mS[r] - mx);
            float l = lS[r] * corr;
#pragma unroll 8
            for (int c = 0; c < 64; c++) {
                float p = __expf(sS[r * 65 + c] - mx);
                sS[r * 65 + c] = p;
                l += p;
            }
            mS[r] = mx; lS[r] = l; cS[r] = corr;
        }
        __syncthreads();

        // ---- rescale accumulators, then O += P @ V ----
#pragma unroll
        for (int i = 0; i < 4; i++) {
            float c = cS[ty * 4 + i];
#pragma unroll
            for (int j = 0; j < 16; j++) oacc[i][j] *= c;
        }
#pragma unroll 4
        for (int kk = 0; kk < 64; kk++) {
            float p[4], v[16];
#pragma unroll
            for (int i = 0; i < 4; i++) p[i] = sS[(ty * 4 + i) * 65 + kk];
#pragma unroll
            for (int j = 0; j < 16; j++) v[j] = vS[kk * 256 + j * 16 + tx];
#pragma unroll
            for (int i = 0; i < 4; i++)
#pragma unroll
                for (int j = 0; j < 16; j++) oacc[i][j] += p[i] * v[j];
        }
    }

    // ---- epilogue: divide by l, write out (coalesced over tx) ----
#pragma unroll
    for (int i = 0; i < 4; i++) {
        int q = q0 + ty * 4 + i;
        float inv = 1.0f / lS[ty * 4 + i];
#pragma unroll
        for (int j = 0; j < 16; j++)
            out[((size_t)b * NQ + q) * DD + j * 16 + tx] = oacc[i][j] * inv;
    }
}

// ---------------------------------------------------------------------------
extern "C" void kernel_launch(void* const* d_in, const int* in_sizes, int n_in,
                              void* d_out, int out_size) {
    const float* query = (const float*)d_in[0];
    const float* key   = (const float*)d_in[1];
    const float* Wq    = (const float*)d_in[2];
    const float* bq    = (const float*)d_in[3];
    const float* Wk    = (const float*)d_in[4];
    const float* bk    = (const float*)d_in[5];
    float* out = (float*)d_out;

    float *p_qproj = nullptr, *p_kproj = nullptr;
    cudaGetSymbolAddress((void**)&p_qproj, g_qproj);
    cudaGetSymbolAddress((void**)&p_kproj, g_kproj);

    size_t flash_smem = (size_t)FL_SMEM_FLOATS * sizeof(float);
    cudaFuncSetAttribute(flash_kernel,
                         cudaFuncAttributeMaxDynamicSharedMemorySize,
                         (int)flash_smem);

    cos_init_kernel<<<8, 256>>>();

    // projections: q (no bias — added after FFT), k (+bk)
    dim3 pgrid(DD / 64, (BB * NQ) / 64);
    proj_kernel<<<pgrid, 256>>>(query, Wq, nullptr, p_qproj, 0);
    proj_kernel<<<pgrid, 256>>>(key,   Wk, bk,      p_kproj, 1);

    // FFT (real part) as cos-table GEMM, + bq
    dim3 fgrid(DD / 64, NQ / 64, BB);
    fft_kernel<<<fgrid, 256>>>(bq);

    // fused scores/softmax/PV, V = original key
    dim3 agrid(NQ / 64, BB);
    flash_kernel<<<agrid, 256, flash_smem>>>(key, out);
}

// round 3
// speedup vs baseline: 2.3990x; 2.3990x over previous
#include <cuda_runtime.h>
#include <cuda_bf16.h>
#include <math.h>
#include <stdint.h>

#define BB 8
#define NQ 2048
#define NK 2048
#define DD 256

// ---------------- static scratch ----------------
__device__ float g_qproj[BB * NQ * DD];
__device__ float g_kproj[BB * NK * DD];
__device__ float g_qfft [BB * NQ * DD];
__device__ float g_scores[(size_t)BB * NQ * NK];
__device__ unsigned g_cosHL[2048];   // low16 = bf16(hi), high16 = bf16(lo)

// ---------------- helpers ----------------
__device__ __forceinline__ unsigned smem_u32(const void* p) {
    unsigned a;
    asm("{ .reg .u64 t; cvta.to.shared.u64 t, %1; cvt.u32.u64 %0, t; }"
        : "=r"(a) : "l"(p));
    return a;
}

__device__ __forceinline__ void ldsm4(unsigned r[4], unsigned addr) {
    asm volatile("ldmatrix.sync.aligned.m8n8.x4.shared.b16 {%0,%1,%2,%3}, [%4];"
                 : "=r"(r[0]), "=r"(r[1]), "=r"(r[2]), "=r"(r[3]) : "r"(addr));
}

__device__ __forceinline__ void mma16816(float d[4], const unsigned a[4],
                                         unsigned b0, unsigned b1) {
    asm volatile(
        "mma.sync.aligned.m16n8k16.row.col.f32.bf16.bf16.f32 "
        "{%0,%1,%2,%3}, {%4,%5,%6,%7}, {%8,%9}, {%0,%1,%2,%3};"
        : "+f"(d[0]), "+f"(d[1]), "+f"(d[2]), "+f"(d[3])
        : "r"(a[0]), "r"(a[1]), "r"(a[2]), "r"(a[3]), "r"(b0), "r"(b1));
}

// smem tile layout: [row][32] bf16, 64B rows, chunk (16B) swizzle c ^= row&3
__device__ __forceinline__ unsigned sw_off(int row, int col) {  // col in [0,32)
    return (unsigned)(row * 64 + ((((col >> 3) ^ (row & 3))) << 4) + ((col & 7) << 1));
}

// smem: buf0 @0, buf1 @32768; each buf: Ahi 0 | Alo 8192 | Bhi 16384 | Blo 24576
// cos table @65536 (8KB)
#define SM_BYTES (65536 + 8192)

__global__ void cos_init_kernel() {
    int i = blockIdx.x * blockDim.x + threadIdx.x;
    if (i < 2048) {
        float c = cospif((float)i / 1024.0f);
        __nv_bfloat16 h = __float2bfloat16(c);
        __nv_bfloat16 l = __float2bfloat16(c - __bfloat162float(h));
        g_cosHL[i] = (unsigned)__bfloat16_as_ushort(h) |
                     ((unsigned)__bfloat16_as_ushort(l) << 16);
    }
}

// ---------------------------------------------------------------------------
// Split-bf16 mma.sync GEMM:  D[m,n] = sum_k A[m,k] * B(n,k)
//   AMODE 0: A gmem row-major [M,K];  AMODE 1: A[m,k]=cos(2pi*m*k/2048)
//   BTR 0: B gmem [N,K];  BTR 1: B gmem [K,N]
//   BIAS 1: += bias[n]
// CTA 128x128, 256 threads (8 warps, 4m x 2n grid, warp tile 32x64), kc=32.
// ---------------------------------------------------------------------------
template<int AMODE, int BTR, int BIAS>
__global__ void __launch_bounds__(256, 1)
gemm_kernel(const float* __restrict__ A, size_t sA,
            const float* __restrict__ B, size_t sB,
            const float* __restrict__ bias,
            float* __restrict__ D, size_t sD,
            int K, int N)
{
    extern __shared__ char sm[];
    const unsigned smb = smem_u32(sm);
    const int tid = threadIdx.x;
    const int lane = tid & 31;
    const int wid = tid >> 5;
    const int m0 = blockIdx.y * 128;
    const int n0 = blockIdx.x * 128;
    const int bz = blockIdx.z;
    const int wm = (wid >> 1) * 32;
    const int wn = (wid & 1) * 64;
    const int l15 = lane & 15;
    const int lh = lane >> 4;

    unsigned* cosS = (unsigned*)(sm + 65536);
    if (AMODE == 1)
        for (int i = tid; i < 2048; i += 256) cosS[i] = g_cosHL[i];

    const float* Ab = A + (size_t)bz * sA;
    const float* Bb = B + (size_t)bz * sB;

    float acc[2][8][4];
#pragma unroll
    for (int t = 0; t < 2; t++)
#pragma unroll
        for (int j = 0; j < 8; j++)
#pragma unroll
            for (int i = 0; i < 4; i++) acc[t][j][i] = 0.0f;

    float va[16], vb[16];
    unsigned vpa[16];

#define LOAD_REGS(c) do {                                                      \
    int k0 = (c) << 5;                                                         \
    if (AMODE == 0) {                                                          \
        const float* ap = Ab + (size_t)m0 * K + k0;                            \
        _Pragma("unroll")                                                      \
        for (int it = 0; it < 16; it++) {                                      \
            int id = tid + it * 256;                                           \
            va[it] = ap[(size_t)(id >> 5) * K + (id & 31)];                    \
        }                                                                      \
    } else {                                                                   \
        _Pragma("unroll")                                                      \
        for (int it = 0; it < 16; it++) {                                      \
            int id = tid + it * 256;                                           \
            int row = id >> 5, col = id & 31;                                  \
            vpa[it] = cosS[((unsigned)(m0 + row) * (unsigned)(k0 + col)) & 2047u]; \
        }                                                                      \
    }                                                                          \
    if (BTR == 0) {                                                            \
        const float* bp = Bb + (size_t)n0 * K + k0;                            \
        _Pragma("unroll")                                                      \
        for (int it = 0; it < 16; it++) {                                      \
            int id = tid + it * 256;                                           \
            vb[it] = bp[(size_t)(id >> 5) * K + (id & 31)];                    \
        }                                                                      \
    } else {                                                                   \
        const float* bp = Bb + (size_t)k0 * N + n0;                            \
        _Pragma("unroll")                                                      \
        for (int it = 0; it < 16; it++) {                                      \
            int id = tid + it * 256;                                           \
            vb[it] = bp[(size_t)(id >> 7) * N + (id & 127)];                   \
        }                                                                      \
    }                                                                          \
} while (0)

#define STORE_SMEM(buf) do {                                                   \
    char* base = sm + (buf) * 32768;                                           \
    _Pragma("unroll")                                                          \
    for (int it = 0; it < 16; it++) {                                          \
        int id = tid + it * 256;                                               \
        int row = id >> 5, col = id & 31;                                      \
        unsigned off = sw_off(row, col);                                       \
        if (AMODE == 0) {                                                      \
            float v = va[it];                                                  \
            __nv_bfloat16 h = __float2bfloat16(v);                             \
            __nv_bfloat16 l = __float2bfloat16(v - __bfloat162float(h));       \
            *(__nv_bfloat16*)(base + off) = h;                                 \
            *(__nv_bfloat16*)(base + 8192 + off) = l;                          \
        } else {                                                               \
            unsigned pk = vpa[it];                                             \
            *(unsigned short*)(base + off) = (unsigned short)pk;               \
            *(unsigned short*)(base + 8192 + off) = (unsigned short)(pk >> 16);\
        }                                                                      \
    }                                                                          \
    _Pragma("unroll")                                                          \
    for (int it = 0; it < 16; it++) {                                          \
        int id = tid + it * 256;                                               \
        int row, col;                                                          \
        if (BTR == 0) { row = id >> 5; col = id & 31; }                        \
        else          { row = id & 127; col = id >> 7; }                       \
        unsigned off = sw_off(row, col);                                       \
        float v = vb[it];                                                      \
        __nv_bfloat16 h = __float2bfloat16(v);                                 \
        __nv_bfloat16 l = __float2bfloat16(v - __bfloat162float(h));           \
        *(__nv_bfloat16*)(base + 16384 + off) = h;                             \
        *(__nv_bfloat16*)(base + 24576 + off) = l;                             \
    }                                                                          \
} while (0)

#define COMPUTE(buf) do {                                                      \
    unsigned ab = smb + (buf) * 32768;                                         \
    _Pragma("unroll")                                                          \
    for (int ks = 0; ks < 2; ks++) {                                           \
        unsigned Ah[2][4], Al[2][4], Bh[4][4], Bl[4][4];                       \
        _Pragma("unroll")                                                      \
        for (int t = 0; t < 2; t++) {                                          \
            int row = wm + 16 * t + l15;                                       \
            unsigned cc = (unsigned)(ks * 2 + lh);                             \
            unsigned so = row * 64 + (((cc ^ (row & 3))) << 4);                \
            ldsm4(Ah[t], ab + so);                                             \
            ldsm4(Al[t], ab + 8192 + so);                                      \
        }                                                                      \
        _Pragma("unroll")                                                      \
        for (int nt = 0; nt < 4; nt++) {                                       \
            int row = wn + 16 * nt + l15;                                      \
            unsigned cc = (unsigned)(ks * 2 + lh);                             \
            unsigned so = row * 64 + (((cc ^ (row & 3))) << 4);                \
            ldsm4(Bh[nt], ab + 16384 + so);                                    \
            ldsm4(Bl[nt], ab + 24576 + so);                                    \
        }                                                                      \
        _Pragma("unroll")                                                      \
        for (int t = 0; t < 2; t++)                                            \
        _Pragma("unroll")                                                      \
        for (int j = 0; j < 8; j++) {                                          \
            int nt = j >> 1, s = j & 1;                                        \
            mma16816(acc[t][j], Ah[t], Bh[nt][s], Bh[nt][2 + s]);              \
            mma16816(acc[t][j], Ah[t], Bl[nt][s], Bl[nt][2 + s]);              \
            mma16816(acc[t][j], Al[t], Bh[nt][s], Bh[nt][2 + s]);              \
        }                                                                      \
    }                                                                          \
} while (0)

    const int NC = K >> 5;
    LOAD_REGS(0);
    STORE_SMEM(0);
    __syncthreads();

#pragma unroll 1
    for (int c = 0; c < NC; c++) {
        int buf = c & 1;
        if (c + 1 < NC) LOAD_REGS(c + 1);
        COMPUTE(buf);
        if (c + 1 < NC) STORE_SMEM(buf ^ 1);
        __syncthreads();
    }

    // ---- epilogue: direct frag stores (float2) ----
    float* Dp = D + (size_t)bz * sD;
#pragma unroll
    for (int t = 0; t < 2; t++) {
#pragma unroll
        for (int j = 0; j < 8; j++) {
            int r0 = m0 + wm + 16 * t + (lane >> 2);
            int col = n0 + wn + 8 * j + 2 * (lane & 3);
            float b0v = 0.0f, b1v = 0.0f;
            if (BIAS) { b0v = __ldg(&bias[col]); b1v = __ldg(&bias[col + 1]); }
            float2 v0 = make_float2(acc[t][j][0] + b0v, acc[t][j][1] + b1v);
            float2 v1 = make_float2(acc[t][j][2] + b0v, acc[t][j][3] + b1v);
            *(float2*)(Dp + (size_t)r0 * N + col) = v0;
            *(float2*)(Dp + (size_t)(r0 + 8) * N + col) = v1;
        }
    }
#undef LOAD_REGS
#undef STORE_SMEM
#undef COMPUTE
}

// ---------------------------------------------------------------------------
// Row softmax over NK=2048 with scale 1/16, in place
// ---------------------------------------------------------------------------
__global__ void softmax_kernel(float* __restrict__ s) {
    size_t row = blockIdx.x;
    float* p = s + row * (size_t)NK;
    int t = threadIdx.x;
    float v[8];
#pragma unroll
    for (int i = 0; i < 8; i++) v[i] = p[t + 256 * i] * 0.0625f;
    float mx = v[0];
#pragma unroll
    for (int i = 1; i < 8; i++) mx = fmaxf(mx, v[i]);
#pragma unroll
    for (int o = 16; o > 0; o >>= 1) mx = fmaxf(mx, __shfl_xor_sync(0xffffffffu, mx, o));
    __shared__ float redm[8], reds[8];
    if ((t & 31) == 0) redm[t >> 5] = mx;
    __syncthreads();
    float m2 = redm[0];
#pragma unroll
    for (int i = 1; i < 8; i++) m2 = fmaxf(m2, redm[i]);
    float sum = 0.0f;
#pragma unroll
    for (int i = 0; i < 8; i++) { v[i] = __expf(v[i] - m2); sum += v[i]; }
#pragma unroll
    for (int o = 16; o > 0; o >>= 1) sum += __shfl_xor_sync(0xffffffffu, sum, o);
    if ((t & 31) == 0) reds[t >> 5] = sum;
    __syncthreads();
    float s2 = 0.0f;
#pragma unroll
    for (int i = 0; i < 8; i++) s2 += reds[i];
    float inv = 1.0f / s2;
#pragma unroll
    for (int i = 0; i < 8; i++) p[t + 256 * i] = v[i] * inv;
}

// ---------------------------------------------------------------------------
extern "C" void kernel_launch(void* const* d_in, const int* in_sizes, int n_in,
                              void* d_out, int out_size) {
    const float* query = (const float*)d_in[0];
    const float* key   = (const float*)d_in[1];
    const float* Wq    = (const float*)d_in[2];
    const float* bq    = (const float*)d_in[3];
    const float* Wk    = (const float*)d_in[4];
    const float* bk    = (const float*)d_in[5];
    float* out = (float*)d_out;

    float *pq, *pk, *pf, *ps;
    cudaGetSymbolAddress((void**)&pq, g_qproj);
    cudaGetSymbolAddress((void**)&pk, g_kproj);
    cudaGetSymbolAddress((void**)&pf, g_qfft);
    cudaGetSymbolAddress((void**)&ps, g_scores);

    cudaFuncSetAttribute(gemm_kernel<0,0,0>, cudaFuncAttributeMaxDynamicSharedMemorySize, SM_BYTES);
    cudaFuncSetAttribute(gemm_kernel<0,0,1>, cudaFuncAttributeMaxDynamicSharedMemorySize, SM_BYTES);
    cudaFuncSetAttribute(gemm_kernel<1,1,1>, cudaFuncAttributeMaxDynamicSharedMemorySize, SM_BYTES);
    cudaFuncSetAttribute(gemm_kernel<0,1,0>, cudaFuncAttributeMaxDynamicSharedMemorySize, SM_BYTES);

    cos_init_kernel<<<8, 256>>>();

    // qproj = query @ Wq^T
    gemm_kernel<0,0,0><<<dim3(2, 128, 1), 256, SM_BYTES>>>(
        query, 0, Wq, 0, nullptr, pq, 0, DD, DD);
    // kproj = key @ Wk^T + bk
    gemm_kernel<0,0,1><<<dim3(2, 128, 1), 256, SM_BYTES>>>(
        key, 0, Wk, 0, bk, pk, 0, DD, DD);
    // qfft = C @ qproj + bq   (A = cos table, B = qproj read [K][N])
    gemm_kernel<1,1,1><<<dim3(2, 16, BB), 256, SM_BYTES>>>(
        nullptr, 0, pq, (size_t)NQ * DD, bq, pf, (size_t)NQ * DD, NQ, DD);
    // scores = qfft @ kproj^T
    gemm_kernel<0,0,0><<<dim3(16, 16, BB), 256, SM_BYTES>>>(
        pf, (size_t)NQ * DD, pk, (size_t)NK * DD, nullptr, ps, (size_t)NQ * NK, DD, NK);
    // softmax rows (scale 1/16)
    softmax_kernel<<<BB * NQ, 256>>>(ps);
    // out = probs @ key (value = key, read [K][N])
    gemm_kernel<0,1,0><<<dim3(2, 16, BB), 256, SM_BYTES>>>(
        ps, (size_t)NQ * NK, key, (size_t)NK * DD, nullptr, out, (size_t)NQ * DD, NK, DD);
}

// round 4
// speedup vs baseline: 4.0256x; 1.6780x over previous
#include <cuda_runtime.h>
#include <cuda_bf16.h>
#include <math.h>
#include <stdint.h>

#define BB 8
#define NQ 2048
#define NK 2048
#define DD 256
typedef __nv_bfloat16 bf16;

// ---------------- static gmem scratch ----------------
__device__ bf16 g_CH[NQ * NQ],      g_CL[NQ * NQ];        // cos matrix
__device__ bf16 g_qH[BB * NQ * DD], g_qL[BB * NQ * DD];   // query split
__device__ bf16 g_kH[BB * NK * DD], g_kL[BB * NK * DD];   // key split
__device__ bf16 g_wqH[DD * DD],     g_wqL[DD * DD];
__device__ bf16 g_wkH[DD * DD],     g_wkL[DD * DD];
__device__ bf16 g_qpTH[DD * BB * NQ], g_qpTL[DD * BB * NQ]; // qprojT [256][16384]
__device__ bf16 g_kpH[BB * NK * DD],  g_kpL[BB * NK * DD];  // kproj
__device__ bf16 g_qfH[BB * NQ * DD],  g_qfL[BB * NQ * DD];  // qfft
__device__ bf16 g_vTH[BB * DD * NK],  g_vTL[BB * DD * NK];  // key^T (value)
__device__ bf16 g_pH[33554432],       g_pL[33554432];       // probs
__device__ float g_scores[33554432];

// ---------------- helpers ----------------
__device__ __forceinline__ unsigned smem_u32(const void* p) {
    unsigned a;
    asm("{ .reg .u64 t; cvta.to.shared.u64 t, %1; cvt.u32.u64 %0, t; }"
        : "=r"(a) : "l"(p));
    return a;
}
__device__ __forceinline__ void ldsm4(unsigned r[4], unsigned addr) {
    asm volatile("ldmatrix.sync.aligned.m8n8.x4.shared.b16 {%0,%1,%2,%3}, [%4];"
                 : "=r"(r[0]), "=r"(r[1]), "=r"(r[2]), "=r"(r[3]) : "r"(addr));
}
__device__ __forceinline__ void mma16816(float d[4], const unsigned a[4],
                                         unsigned b0, unsigned b1) {
    asm volatile(
        "mma.sync.aligned.m16n8k16.row.col.f32.bf16.bf16.f32 "
        "{%0,%1,%2,%3}, {%4,%5,%6,%7}, {%8,%9}, {%0,%1,%2,%3};"
        : "+f"(d[0]), "+f"(d[1]), "+f"(d[2]), "+f"(d[3])
        : "r"(a[0]), "r"(a[1]), "r"(a[2]), "r"(a[3]), "r"(b0), "r"(b1));
}
__device__ __forceinline__ void cpa(unsigned dst, const void* src) {
    asm volatile("cp.async.cg.shared.global [%0], [%1], 16;" :: "r"(dst), "l"(src));
}

// smem: 2 bufs x 96KB; buf: AH 0 | AL 16K | BH 32K | BL 64K. rows = 128B, SW128.
#define SM_BYTES (2 * 98304)

// ---------------- prep kernels ----------------
__global__ void split_kernel(const float* __restrict__ x, bf16* __restrict__ h,
                             bf16* __restrict__ l, int n) {
    int i = blockIdx.x * blockDim.x + threadIdx.x;
    if (i < n) {
        float v = x[i];
        bf16 hv = __float2bfloat16(v);
        h[i] = hv;
        l[i] = __float2bfloat16(v - __bfloat162float(hv));
    }
}

__global__ void cinit_kernel() {
    int i = blockIdx.x * blockDim.x + threadIdx.x;   // 2048*2048
    int m = i >> 11, k = i & 2047;
    float c = cospif((float)((m * k) & 2047) * (1.0f / 1024.0f));
    bf16 h = __float2bfloat16(c);
    g_CH[i] = h;
    g_CL[i] = __float2bfloat16(c - __bfloat162float(h));
}

__global__ void transpose_kernel(const float* __restrict__ key,
                                 bf16* __restrict__ oH, bf16* __restrict__ oL) {
    __shared__ float ts[32][33];
    int b = blockIdx.z, n0 = blockIdx.x * 32, d0 = blockIdx.y * 32;
    const float* kb = key + (size_t)b * NK * DD;
#pragma unroll
    for (int i = 0; i < 4; i++) {
        int r = threadIdx.y + i * 8;
        ts[r][threadIdx.x] = kb[(size_t)(n0 + r) * DD + d0 + threadIdx.x];
    }
    __syncthreads();
#pragma unroll
    for (int i = 0; i < 4; i++) {
        int d = threadIdx.y + i * 8;
        float v = ts[threadIdx.x][d];
        size_t off = (size_t)b * DD * NK + (size_t)(d0 + d) * NK + n0 + threadIdx.x;
        bf16 h = __float2bfloat16(v);
        oH[off] = h;
        oL[off] = __float2bfloat16(v - __bfloat162float(h));
    }
}

// ---------------------------------------------------------------------------
// Split-bf16 mma.sync GEMM, all operands pre-split bf16 hi/lo, cp.async loads.
// D[m,n] = sum_k A[m,k]*B[n,k] (+bias[n]).  CTA 128m x 256n, kc=64, 256 thr,
// 8 warps as 2m x 4n of 64x64 warp tiles.  OUT: 0 fp32 D, 1 bf16 hi/lo.
// ---------------------------------------------------------------------------
template<int OUT>
__global__ void __launch_bounds__(256, 1)
gemm_kernel(const bf16* __restrict__ AH, const bf16* __restrict__ AL, size_t sA,
            const bf16* __restrict__ BH, const bf16* __restrict__ BL, size_t sB,
            int rB,
            const float* __restrict__ bias,
            float* __restrict__ D, bf16* __restrict__ DH, bf16* __restrict__ DL,
            size_t sD, int oS, int K)
{
    extern __shared__ char sm[];
    const unsigned smb = smem_u32(sm);
    const int tid = threadIdx.x;
    const int lane = tid & 31;
    const int wid = tid >> 5;
    const int m0 = blockIdx.y * 128;
    const int n0 = blockIdx.x * 256;
    const int bz = blockIdx.z;
    const int wm = (wid & 1) * 64;
    const int wn = (wid >> 1) * 64;
    const int l15 = lane & 15;
    const int lh = lane >> 4;

    const bf16* AHb = AH + bz * sA;
    const bf16* ALb = AL + bz * sA;
    const bf16* BHb = BH + bz * sB;
    const bf16* BLb = BL + bz * sB;

    float acc[4][8][4];
#pragma unroll
    for (int t = 0; t < 4; t++)
#pragma unroll
        for (int j = 0; j < 8; j++)
#pragma unroll
            for (int i = 0; i < 4; i++) acc[t][j][i] = 0.0f;

    const int rw = tid >> 3, ch = tid & 7;

    auto ISSUE = [&](int c, int buf) {
        const int ke = (c << 6) + ch * 8;
        const unsigned bufb = smb + buf * 98304;
#pragma unroll
        for (int it = 0; it < 4; it++) {
            int r = rw + it * 32;
            unsigned so = bufb + r * 128 + ((ch ^ (r & 7)) << 4);
            size_t go = (size_t)(m0 + r) * K + ke;
            cpa(so, AHb + go);
            cpa(so + 16384, ALb + go);
        }
#pragma unroll
        for (int it = 0; it < 8; it++) {
            int r = rw + it * 32;
            unsigned so = bufb + 32768 + r * 128 + ((ch ^ (r & 7)) << 4);
            size_t go = (size_t)(n0 + r) * rB + ke;
            cpa(so, BHb + go);
            cpa(so + 32768, BLb + go);
        }
        asm volatile("cp.async.commit_group;" ::: "memory");
    };

    auto COMPUTE = [&](int buf) {
        const unsigned ab = smb + buf * 98304;
#pragma unroll
        for (int ks = 0; ks < 4; ks++) {
            unsigned Ah[4][4], Al[4][4], Bh[4][4], Bl[4][4];
#pragma unroll
            for (int t = 0; t < 4; t++) {
                int row = wm + 16 * t + l15;
                unsigned so = ab + row * 128 + (((ks * 2 + lh) ^ (row & 7)) << 4);
                ldsm4(Ah[t], so);
                ldsm4(Al[t], so + 16384);
            }
#pragma unroll
            for (int nt = 0; nt < 4; nt++) {
                int row = wn + 16 * nt + l15;
                unsigned so = ab + 32768 + row * 128 +
                              (((ks * 2 + lh) ^ (row & 7)) << 4);
                ldsm4(Bh[nt], so);
                ldsm4(Bl[nt], so + 32768);
            }
#pragma unroll
            for (int t = 0; t < 4; t++)
#pragma unroll
                for (int nt = 0; nt < 4; nt++)
#pragma unroll
                    for (int s = 0; s < 2; s++) {
                        int j = nt * 2 + s;
                        mma16816(acc[t][j], Ah[t], Bh[nt][s], Bh[nt][2 + s]);
                        mma16816(acc[t][j], Ah[t], Bl[nt][s], Bl[nt][2 + s]);
                        mma16816(acc[t][j], Al[t], Bh[nt][s], Bh[nt][2 + s]);
                    }
        }
    };

    const int NC = K >> 6;
    ISSUE(0, 0);
#pragma unroll 1
    for (int c = 0; c < NC; c++) {
        int buf = c & 1;
        if (c + 1 < NC) {
            ISSUE(c + 1, buf ^ 1);
            asm volatile("cp.async.wait_group 1;" ::: "memory");
        } else {
            asm volatile("cp.async.wait_group 0;" ::: "memory");
        }
        __syncthreads();
        COMPUTE(buf);
        __syncthreads();
    }

    // ---- epilogue ----
#pragma unroll
    for (int t = 0; t < 4; t++) {
#pragma unroll
        for (int j = 0; j < 8; j++) {
            int r0 = m0 + wm + 16 * t + (lane >> 2);
            int col = n0 + wn + 8 * j + 2 * (lane & 3);
            float b0v = 0.0f, b1v = 0.0f;
            if (bias) { b0v = __ldg(&bias[col]); b1v = __ldg(&bias[col + 1]); }
            float v0 = acc[t][j][0] + b0v, v1 = acc[t][j][1] + b1v;
            float v2 = acc[t][j][2] + b0v, v3 = acc[t][j][3] + b1v;
            if (OUT == 0) {
                float* Dp = D + bz * sD;
                *(float2*)(Dp + (size_t)r0 * oS + col) = make_float2(v0, v1);
                *(float2*)(Dp + (size_t)(r0 + 8) * oS + col) = make_float2(v2, v3);
            } else {
                bf16* Hp = DH + bz * sD;
                bf16* Lp = DL + bz * sD;
                __nv_bfloat162 h01, h23, l01, l23;
                h01.x = __float2bfloat16(v0); h01.y = __float2bfloat16(v1);
                h23.x = __float2bfloat16(v2); h23.y = __float2bfloat16(v3);
                l01.x = __float2bfloat16(v0 - __bfloat162float(h01.x));
                l01.y = __float2bfloat16(v1 - __bfloat162float(h01.y));
                l23.x = __float2bfloat16(v2 - __bfloat162float(h23.x));
                l23.y = __float2bfloat16(v3 - __bfloat162float(h23.y));
                *(__nv_bfloat162*)(Hp + (size_t)r0 * oS + col) = h01;
                *(__nv_bfloat162*)(Lp + (size_t)r0 * oS + col) = l01;
                *(__nv_bfloat162*)(Hp + (size_t)(r0 + 8) * oS + col) = h23;
                *(__nv_bfloat162*)(Lp + (size_t)(r0 + 8) * oS + col) = l23;
            }
        }
    }
}

// ---------------------------------------------------------------------------
// Row softmax over NK with scale 1/16; emits probs as bf16 hi/lo
// ---------------------------------------------------------------------------
__global__ void softmax_kernel(const float* __restrict__ s,
                               bf16* __restrict__ pH, bf16* __restrict__ pL) {
    size_t row = blockIdx.x;
    const float* p = s + row * (size_t)NK;
    int t = threadIdx.x;
    float v[8];
#pragma unroll
    for (int i = 0; i < 8; i++) v[i] = p[t + 256 * i] * 0.0625f;
    float mx = v[0];
#pragma unroll
    for (int i = 1; i < 8; i++) mx = fmaxf(mx, v[i]);
#pragma unroll
    for (int o = 16; o > 0; o >>= 1) mx = fmaxf(mx, __shfl_xor_sync(0xffffffffu, mx, o));
    __shared__ float redm[8], reds[8];
    if ((t & 31) == 0) redm[t >> 5] = mx;
    __syncthreads();
    float m2 = redm[0];
#pragma unroll
    for (int i = 1; i < 8; i++) m2 = fmaxf(m2, redm[i]);
    float sum = 0.0f;
#pragma unroll
    for (int i = 0; i < 8; i++) { v[i] = __expf(v[i] - m2); sum += v[i]; }
#pragma unroll
    for (int o = 16; o > 0; o >>= 1) sum += __shfl_xor_sync(0xffffffffu, sum, o);
    if ((t & 31) == 0) reds[t >> 5] = sum;
    __syncthreads();
    float s2 = 0.0f;
#pragma unroll
    for (int i = 0; i < 8; i++) s2 += reds[i];
    float inv = 1.0f / s2;
    size_t base = row * (size_t)NK + t;
#pragma unroll
    for (int i = 0; i < 8; i++) {
        float pv = v[i] * inv;
        bf16 h = __float2bfloat16(pv);
        pH[base + 256 * i] = h;
        pL[base + 256 * i] = __float2bfloat16(pv - __bfloat162float(h));
    }
}

// ---------------------------------------------------------------------------
extern "C" void kernel_launch(void* const* d_in, const int* in_sizes, int n_in,
                              void* d_out, int out_size) {
    const float* query = (const float*)d_in[0];
    const float* key   = (const float*)d_in[1];
    const float* Wq    = (const float*)d_in[2];
    const float* bq    = (const float*)d_in[3];
    const float* Wk    = (const float*)d_in[4];
    const float* bk    = (const float*)d_in[5];
    float* out = (float*)d_out;

#define SYM(p, s) void* p; cudaGetSymbolAddress(&p, s)
    SYM(qH, g_qH);   SYM(qL, g_qL);   SYM(kH, g_kH);   SYM(kL, g_kL);
    SYM(wqH, g_wqH); SYM(wqL, g_wqL); SYM(wkH, g_wkH); SYM(wkL, g_wkL);
    SYM(qpTH, g_qpTH); SYM(qpTL, g_qpTL);
    SYM(kpH, g_kpH); SYM(kpL, g_kpL);
    SYM(qfH, g_qfH); SYM(qfL, g_qfL);
    SYM(vTH, g_vTH); SYM(vTL, g_vTL);
    SYM(pH, g_pH);   SYM(pL, g_pL);
    SYM(CH, g_CH);   SYM(CL, g_CL);
    SYM(sc, g_scores);
#undef SYM

    cudaFuncSetAttribute(gemm_kernel<0>, cudaFuncAttributeMaxDynamicSharedMemorySize, SM_BYTES);
    cudaFuncSetAttribute(gemm_kernel<1>, cudaFuncAttributeMaxDynamicSharedMemorySize, SM_BYTES);

    // preps
    cinit_kernel<<<16384, 256>>>();
    split_kernel<<<16384, 256>>>(query, (bf16*)qH, (bf16*)qL, BB * NQ * DD);
    split_kernel<<<16384, 256>>>(key,   (bf16*)kH, (bf16*)kL, BB * NK * DD);
    split_kernel<<<256, 256>>>(Wq, (bf16*)wqH, (bf16*)wqL, DD * DD);
    split_kernel<<<256, 256>>>(Wk, (bf16*)wkH, (bf16*)wkL, DD * DD);
    transpose_kernel<<<dim3(NK / 32, DD / 32, BB), dim3(32, 8)>>>(
        key, (bf16*)vTH, (bf16*)vTL);

    // G1: qprojT[d, m] = Wq @ query^T   (M=256, N=16384, K=256)
    gemm_kernel<1><<<dim3(64, 2, 1), 256, SM_BYTES>>>(
        (bf16*)wqH, (bf16*)wqL, 0, (bf16*)qH, (bf16*)qL, 0, DD,
        nullptr, nullptr, (bf16*)qpTH, (bf16*)qpTL, 0, BB * NQ, DD);
    // G2: kproj = key @ Wk^T + bk       (M=16384, N=256, K=256)
    gemm_kernel<1><<<dim3(1, 128, 1), 256, SM_BYTES>>>(
        (bf16*)kH, (bf16*)kL, 0, (bf16*)wkH, (bf16*)wkL, 0, DD,
        bk, nullptr, (bf16*)kpH, (bf16*)kpL, 0, DD, DD);
    // G3: qfft = C @ qprojT^T + bq      (per b: M=2048, N=256, K=2048)
    gemm_kernel<1><<<dim3(1, 16, BB), 256, SM_BYTES>>>(
        (bf16*)CH, (bf16*)CL, 0, (bf16*)qpTH, (bf16*)qpTL, NQ, BB * NQ,
        bq, nullptr, (bf16*)qfH, (bf16*)qfL, (size_t)NQ * DD, DD, NQ);
    // G4: scores = qfft @ kproj^T       (per b: M=2048, N=2048, K=256)
    gemm_kernel<0><<<dim3(8, 16, BB), 256, SM_BYTES>>>(
        (bf16*)qfH, (bf16*)qfL, (size_t)NQ * DD,
        (bf16*)kpH, (bf16*)kpL, (size_t)NK * DD, DD,
        nullptr, (float*)sc, nullptr, nullptr, (size_t)NQ * NK, NK, DD);
    // softmax -> probs hi/lo
    softmax_kernel<<<BB * NQ, 256>>>((float*)sc, (bf16*)pH, (bf16*)pL);
    // G5: out = probs @ keyT^T          (per b: M=2048, N=256, K=2048)
    gemm_kernel<0><<<dim3(1, 16, BB), 256, SM_BYTES>>>(
        (bf16*)pH, (bf16*)pL, (size_t)NQ * NK,
        (bf16*)vTH, (bf16*)vTL, (size_t)DD * NK, NK,
        nullptr, out, nullptr, nullptr, (size_t)NQ * DD, DD, NK);
}

// round 5
// speedup vs baseline: 7.0795x; 1.7586x over previous
#include <cuda_runtime.h>
#include <cuda_bf16.h>
#include <math.h>
#include <stdint.h>

#define BB 8
#define NQ 2048
#define NK 2048
#define DD 256
#define MP 1152              // padded half-row count (9 * 128), rows 0..1024 real
typedef __nv_bfloat16 bf16;

// ---------------- static gmem scratch ----------------
__device__ bf16 g_CH[MP * 1024],      g_CL[MP * 1024];       // folded cos matrix
__device__ bf16 g_qH[BB * NQ * DD],   g_qL[BB * NQ * DD];
__device__ bf16 g_kH[BB * NK * DD],   g_kL[BB * NK * DD];
__device__ bf16 g_wqH[DD * DD],       g_wqL[DD * DD];
__device__ bf16 g_wkH[DD * DD],       g_wkL[DD * DD];
__device__ bf16 g_qpTH[DD * BB * NQ], g_qpTL[DD * BB * NQ];  // qprojT [256][16384]
__device__ bf16 g_qpFH[DD * BB * 1024], g_qpFL[DD * BB * 1024]; // folded qprojT
__device__ float g_q1024[BB * DD];                            // qproj row 1024
__device__ bf16 g_kpH[BB * NK * DD],  g_kpL[BB * NK * DD];   // kproj
__device__ bf16 g_qfH[BB * MP * DD],  g_qfL[BB * MP * DD];   // qfft (half rows)
__device__ bf16 g_vTH[BB * DD * NK],  g_vTL[BB * DD * NK];   // key^T (value)
__device__ float g_scores[(size_t)BB * MP * NK];              // 18.9M
__device__ bf16 g_pH[(size_t)BB * MP * NK], g_pL[(size_t)BB * MP * NK];
__device__ float g_op[16 * MP * DD];                          // split-K partials

// ---------------- helpers ----------------
__device__ __forceinline__ unsigned smem_u32(const void* p) {
    unsigned a;
    asm("{ .reg .u64 t; cvta.to.shared.u64 t, %1; cvt.u32.u64 %0, t; }"
        : "=r"(a) : "l"(p));
    return a;
}
__device__ __forceinline__ void ldsm4(unsigned r[4], unsigned addr) {
    asm volatile("ldmatrix.sync.aligned.m8n8.x4.shared.b16 {%0,%1,%2,%3}, [%4];"
                 : "=r"(r[0]), "=r"(r[1]), "=r"(r[2]), "=r"(r[3]) : "r"(addr));
}
__device__ __forceinline__ void mma16816(float d[4], const unsigned a[4],
                                         unsigned b0, unsigned b1) {
    asm volatile(
        "mma.sync.aligned.m16n8k16.row.col.f32.bf16.bf16.f32 "
        "{%0,%1,%2,%3}, {%4,%5,%6,%7}, {%8,%9}, {%0,%1,%2,%3};"
        : "+f"(d[0]), "+f"(d[1]), "+f"(d[2]), "+f"(d[3])
        : "r"(a[0]), "r"(a[1]), "r"(a[2]), "r"(a[3]), "r"(b0), "r"(b1));
}
__device__ __forceinline__ void cpa(unsigned dst, const void* src) {
    asm volatile("cp.async.cg.shared.global [%0], [%1], 16;" :: "r"(dst), "l"(src));
}

// ---------------- prep kernels ----------------
__global__ void split_kernel(const float* __restrict__ x, bf16* __restrict__ h,
                             bf16* __restrict__ l, int n) {
    int i = blockIdx.x * blockDim.x + threadIdx.x;
    if (i < n) {
        float v = x[i];
        bf16 hv = __float2bfloat16(v);
        h[i] = hv;
        l[i] = __float2bfloat16(v - __bfloat162float(hv));
    }
}

__global__ void cinit_kernel() {   // C[m][k], m<MP, k<1024
    int i = blockIdx.x * blockDim.x + threadIdx.x;
    if (i < MP * 1024) {
        int m = i >> 10, k = i & 1023;
        float c = cospif((float)((m * k) & 2047) * (1.0f / 1024.0f));
        bf16 h = __float2bfloat16(c);
        g_CH[i] = h;
        g_CL[i] = __float2bfloat16(c - __bfloat162float(h));
    }
}

__global__ void transpose_kernel(const float* __restrict__ key,
                                 bf16* __restrict__ oH, bf16* __restrict__ oL) {
    __shared__ float ts[32][33];
    int b = blockIdx.z, n0 = blockIdx.x * 32, d0 = blockIdx.y * 32;
    const float* kb = key + (size_t)b * NK * DD;
#pragma unroll
    for (int i = 0; i < 4; i++) {
        int r = threadIdx.y + i * 8;
        ts[r][threadIdx.x] = kb[(size_t)(n0 + r) * DD + d0 + threadIdx.x];
    }
    __syncthreads();
#pragma unroll
    for (int i = 0; i < 4; i++) {
        int d = threadIdx.y + i * 8;
        float v = ts[threadIdx.x][d];
        size_t off = (size_t)b * DD * NK + (size_t)(d0 + d) * NK + n0 + threadIdx.x;
        bf16 h = __float2bfloat16(v);
        oH[off] = h;
        oL[off] = __float2bfloat16(v - __bfloat162float(h));
    }
}

// qpF[d][b*1024+k] = qpT[d][b*2048+k] (+ qpT[d][b*2048+2048-k] for k>0)
__global__ void fold_kernel() {
    int i = blockIdx.x * blockDim.x + threadIdx.x;
    if (i >= DD * BB * 1024) return;
    int d = i >> 13;             // /8192
    int r = i & 8191;
    int b = r >> 10, k = r & 1023;
    size_t base = (size_t)d * (BB * NQ) + b * 2048;
    float v = __bfloat162float(g_qpTH[base + k]) + __bfloat162float(g_qpTL[base + k]);
    if (k > 0) {
        v += __bfloat162float(g_qpTH[base + 2048 - k]) +
             __bfloat162float(g_qpTL[base + 2048 - k]);
    }
    bf16 h = __float2bfloat16(v);
    g_qpFH[i] = h;
    g_qpFL[i] = __float2bfloat16(v - __bfloat162float(h));
}

__global__ void q1024_kernel() {
    int i = blockIdx.x * blockDim.x + threadIdx.x;   // BB*DD
    if (i < BB * DD) {
        int b = i >> 8, d = i & 255;
        size_t off = (size_t)d * (BB * NQ) + b * 2048 + 1024;
        g_q1024[i] = __bfloat162float(g_qpTH[off]) + __bfloat162float(g_qpTL[off]);
    }
}

// ---------------------------------------------------------------------------
// Split-bf16 mma.sync GEMM. D[m,n] = sum_k A[m,k]*B[n,k] (+bias[n]) (+(-1)^m fix[n]).
// CTA 128m x NTn, kc=64, 256 thr. NT=256: warps 2m x 4n (64x64). NT=128: 4m x 2n (32x64).
// OUT: 0 fp32, 1 bf16 hi/lo. SPLITK: bz = b + 8*ks, operand k offset = ks*K.
// ---------------------------------------------------------------------------
template<int OUT, int NT, int FIX, int SPLITK>
__global__ void __launch_bounds__(256, 1)
gemm_kernel(const bf16* __restrict__ AH, const bf16* __restrict__ AL,
            size_t sA, int rA,
            const bf16* __restrict__ BH, const bf16* __restrict__ BL,
            size_t sB, int rB,
            const float* __restrict__ bias, const float* __restrict__ fix,
            float* __restrict__ D, bf16* __restrict__ DH, bf16* __restrict__ DL,
            size_t sD, int oS, int K)
{
    constexpr int TM   = (NT == 256) ? 4 : 2;        // m16 tiles per warp
    constexpr int NB   = NT / 32;                    // B load iterations
    constexpr int BSZ  = NT * 128;                   // B plane bytes
    constexpr int BUFS = 32768 + 2 * BSZ;            // buffer stride

    extern __shared__ char sm[];
    const unsigned smb = smem_u32(sm);
    const int tid = threadIdx.x;
    const int lane = tid & 31;
    const int wid = tid >> 5;
    const int m0 = blockIdx.y * 128;
    const int n0 = blockIdx.x * NT;
    const int bz = blockIdx.z;
    const int b  = SPLITK ? (bz & 7) : bz;
    const int koff = SPLITK ? (bz >> 3) * K : 0;
    const int wm = (NT == 256) ? (wid & 1) * 64 : (wid & 3) * 32;
    const int wn = (NT == 256) ? (wid >> 1) * 64 : (wid >> 2) * 64;
    const int l15 = lane & 15;
    const int lh = lane >> 4;

    const bf16* AHb = AH + b * sA + koff;
    const bf16* ALb = AL + b * sA + koff;
    const bf16* BHb = BH + b * sB + koff;
    const bf16* BLb = BL + b * sB + koff;

    float acc[TM][8][4];
#pragma unroll
    for (int t = 0; t < TM; t++)
#pragma unroll
        for (int j = 0; j < 8; j++)
#pragma unroll
            for (int i = 0; i < 4; i++) acc[t][j][i] = 0.0f;

    const int rw = tid >> 3, ch = tid & 7;

    auto ISSUE = [&](int c, int buf) {
        const int ke = (c << 6) + ch * 8;
        const unsigned bufb = smb + buf * BUFS;
#pragma unroll
        for (int it = 0; it < 4; it++) {
            int r = rw + it * 32;
            unsigned so = bufb + r * 128 + ((ch ^ (r & 7)) << 4);
            size_t go = (size_t)(m0 + r) * rA + ke;
            cpa(so, AHb + go);
            cpa(so + 16384, ALb + go);
        }
#pragma unroll
        for (int it = 0; it < NB; it++) {
            int r = rw + it * 32;
            unsigned so = bufb + 32768 + r * 128 + ((ch ^ (r & 7)) << 4);
            size_t go = (size_t)(n0 + r) * rB + ke;
            cpa(so, BHb + go);
            cpa(so + BSZ, BLb + go);
        }
        asm volatile("cp.async.commit_group;" ::: "memory");
    };

    auto COMPUTE = [&](int buf) {
        const unsigned ab = smb + buf * BUFS;
#pragma unroll
        for (int ks = 0; ks < 4; ks++) {
            unsigned Ah[TM][4], Al[TM][4], Bh[4][4], Bl[4][4];
#pragma unroll
            for (int t = 0; t < TM; t++) {
                int row = wm + 16 * t + l15;
                unsigned so = ab + row * 128 + (((ks * 2 + lh) ^ (row & 7)) << 4);
                ldsm4(Ah[t], so);
                ldsm4(Al[t], so + 16384);
            }
#pragma unroll
            for (int nt = 0; nt < 4; nt++) {
                int row = wn + 16 * nt + l15;
                unsigned so = ab + 32768 + row * 128 +
                              (((ks * 2 + lh) ^ (row & 7)) << 4);
                ldsm4(Bh[nt], so);
                ldsm4(Bl[nt], so + BSZ);
            }
#pragma unroll
            for (int t = 0; t < TM; t++)
#pragma unroll
                for (int nt = 0; nt < 4; nt++)
#pragma unroll
                    for (int s = 0; s < 2; s++) {
                        int j = nt * 2 + s;
                        mma16816(acc[t][j], Ah[t], Bh[nt][s], Bh[nt][2 + s]);
                        mma16816(acc[t][j], Ah[t], Bl[nt][s], Bl[nt][2 + s]);
                        mma16816(acc[t][j], Al[t], Bh[nt][s], Bh[nt][2 + s]);
                    }
        }
    };

    const int NC = K >> 6;
    ISSUE(0, 0);
#pragma unroll 1
    for (int c = 0; c < NC; c++) {
        int buf = c & 1;
        if (c + 1 < NC) {
            ISSUE(c + 1, buf ^ 1);
            asm volatile("cp.async.wait_group 1;" ::: "memory");
        } else {
            asm volatile("cp.async.wait_group 0;" ::: "memory");
        }
        __syncthreads();
        COMPUTE(buf);
        __syncthreads();
    }

    // ---- epilogue ----
#pragma unroll
    for (int t = 0; t < TM; t++) {
#pragma unroll
        for (int j = 0; j < 8; j++) {
            int r0 = m0 + wm + 16 * t + (lane >> 2);
            int col = n0 + wn + 8 * j + 2 * (lane & 3);
            float b0v = 0.0f, b1v = 0.0f;
            if (bias) { b0v = __ldg(&bias[col]); b1v = __ldg(&bias[col + 1]); }
            if (FIX) {
                const float* fx = fix + b * DD;
                float sg = (r0 & 1) ? -1.0f : 1.0f;
                b0v += sg * __ldg(&fx[col]);
                b1v += sg * __ldg(&fx[col + 1]);
            }
            float v0 = acc[t][j][0] + b0v, v1 = acc[t][j][1] + b1v;
            float v2 = acc[t][j][2] + b0v, v3 = acc[t][j][3] + b1v;
            if (OUT == 0) {
                float* Dp = D + bz * sD;
                *(float2*)(Dp + (size_t)r0 * oS + col) = make_float2(v0, v1);
                *(float2*)(Dp + (size_t)(r0 + 8) * oS + col) = make_float2(v2, v3);
            } else {
                bf16* Hp = DH + bz * sD;
                bf16* Lp = DL + bz * sD;
                __nv_bfloat162 h01, h23, l01, l23;
                h01.x = __float2bfloat16(v0); h01.y = __float2bfloat16(v1);
                h23.x = __float2bfloat16(v2); h23.y = __float2bfloat16(v3);
                l01.x = __float2bfloat16(v0 - __bfloat162float(h01.x));
                l01.y = __float2bfloat16(v1 - __bfloat162float(h01.y));
                l23.x = __float2bfloat16(v2 - __bfloat162float(h23.x));
                l23.y = __float2bfloat16(v3 - __bfloat162float(h23.y));
                *(__nv_bfloat162*)(Hp + (size_t)r0 * oS + col) = h01;
                *(__nv_bfloat162*)(Lp + (size_t)r0 * oS + col) = l01;
                *(__nv_bfloat162*)(Hp + (size_t)(r0 + 8) * oS + col) = h23;
                *(__nv_bfloat162*)(Lp + (size_t)(r0 + 8) * oS + col) = l23;
            }
        }
    }
}

// ---------------------------------------------------------------------------
// Row softmax over NK with scale 1/16; emits probs as bf16 hi/lo
// ---------------------------------------------------------------------------
__global__ void softmax_kernel(const float* __restrict__ s,
                               bf16* __restrict__ pH, bf16* __restrict__ pL) {
    size_t row = blockIdx.x;
    const float* p = s + row * (size_t)NK;
    int t = threadIdx.x;
    float v[8];
#pragma unroll
    for (int i = 0; i < 8; i++) v[i] = p[t + 256 * i] * 0.0625f;
    float mx = v[0];
#pragma unroll
    for (int i = 1; i < 8; i++) mx = fmaxf(mx, v[i]);
#pragma unroll
    for (int o = 16; o > 0; o >>= 1) mx = fmaxf(mx, __shfl_xor_sync(0xffffffffu, mx, o));
    __shared__ float redm[8], reds[8];
    if ((t & 31) == 0) redm[t >> 5] = mx;
    __syncthreads();
    float m2 = redm[0];
#pragma unroll
    for (int i = 1; i < 8; i++) m2 = fmaxf(m2, redm[i]);
    float sum = 0.0f;
#pragma unroll
    for (int i = 0; i < 8; i++) { v[i] = __expf(v[i] - m2); sum += v[i]; }
#pragma unroll
    for (int o = 16; o > 0; o >>= 1) sum += __shfl_xor_sync(0xffffffffu, sum, o);
    if ((t & 31) == 0) reds[t >> 5] = sum;
    __syncthreads();
    float s2 = 0.0f;
#pragma unroll
    for (int i = 0; i < 8; i++) s2 += reds[i];
    float inv = 1.0f / s2;
    size_t base = row * (size_t)NK + t;
#pragma unroll
    for (int i = 0; i < 8; i++) {
        float pv = v[i] * inv;
        bf16 h = __float2bfloat16(pv);
        pH[base + 256 * i] = h;
        pL[base + 256 * i] = __float2bfloat16(pv - __bfloat162float(h));
    }
}

// ---------------------------------------------------------------------------
// combine split-K partials + mirror rows: out[b][m] = out[b][2048-m]
// grid (1025, BB), 256 threads = d
// ---------------------------------------------------------------------------
__global__ void combine_kernel(const float* __restrict__ op, float* __restrict__ out) {
    int m = blockIdx.x, b = blockIdx.y, d = threadIdx.x;
    size_t src = ((size_t)b * MP + m) * DD + d;
    float v = op[src] + op[src + (size_t)8 * MP * DD];
    out[((size_t)b * NQ + m) * DD + d] = v;
    if (m >= 1 && m <= 1023)
        out[((size_t)b * NQ + 2048 - m) * DD + d] = v;
}

// ---------------------------------------------------------------------------
extern "C" void kernel_launch(void* const* d_in, const int* in_sizes, int n_in,
                              void* d_out, int out_size) {
    const float* query = (const float*)d_in[0];
    const float* key   = (const float*)d_in[1];
    const float* Wq    = (const float*)d_in[2];
    const float* bq    = (const float*)d_in[3];
    const float* Wk    = (const float*)d_in[4];
    const float* bk    = (const float*)d_in[5];
    float* out = (float*)d_out;

#define SYM(p, s) void* p; cudaGetSymbolAddress(&p, s)
    SYM(qH, g_qH);   SYM(qL, g_qL);   SYM(kH, g_kH);   SYM(kL, g_kL);
    SYM(wqH, g_wqH); SYM(wqL, g_wqL); SYM(wkH, g_wkH); SYM(wkL, g_wkL);
    SYM(qpTH, g_qpTH); SYM(qpTL, g_qpTL);
    SYM(qpFH, g_qpFH); SYM(qpFL, g_qpFL);
    SYM(q1024, g_q1024);
    SYM(kpH, g_kpH); SYM(kpL, g_kpL);
    SYM(qfH, g_qfH); SYM(qfL, g_qfL);
    SYM(vTH, g_vTH); SYM(vTL, g_vTL);
    SYM(pH, g_pH);   SYM(pL, g_pL);
    SYM(CH, g_CH);   SYM(CL, g_CL);
    SYM(sc, g_scores); SYM(op, g_op);
#undef SYM

    const int SM256 = 2 * (32768 + 2 * 256 * 128);   // 196608
    const int SM128 = 2 * (32768 + 2 * 128 * 128);   // 131072
    cudaFuncSetAttribute((const void*)gemm_kernel<1,256,0,0>, cudaFuncAttributeMaxDynamicSharedMemorySize, SM256);
    cudaFuncSetAttribute((const void*)gemm_kernel<0,256,0,0>, cudaFuncAttributeMaxDynamicSharedMemorySize, SM256);
    cudaFuncSetAttribute((const void*)gemm_kernel<1,128,1,0>, cudaFuncAttributeMaxDynamicSharedMemorySize, SM128);
    cudaFuncSetAttribute((const void*)gemm_kernel<0,128,0,1>, cudaFuncAttributeMaxDynamicSharedMemorySize, SM128);

    // preps
    cinit_kernel<<<(MP * 1024 + 255) / 256, 256>>>();
    split_kernel<<<16384, 256>>>(query, (bf16*)qH, (bf16*)qL, BB * NQ * DD);
    split_kernel<<<16384, 256>>>(key,   (bf16*)kH, (bf16*)kL, BB * NK * DD);
    split_kernel<<<256, 256>>>(Wq, (bf16*)wqH, (bf16*)wqL, DD * DD);
    split_kernel<<<256, 256>>>(Wk, (bf16*)wkH, (bf16*)wkL, DD * DD);
    transpose_kernel<<<dim3(NK / 32, DD / 32, BB), dim3(32, 8)>>>(
        key, (bf16*)vTH, (bf16*)vTL);

    // G1: qprojT[d, b*m] = Wq @ query^T    (M=256, N=16384, K=256)
    gemm_kernel<1,256,0,0><<<dim3(64, 2, 1), 256, SM256>>>(
        (bf16*)wqH, (bf16*)wqL, 0, DD, (bf16*)qH, (bf16*)qL, 0, DD,
        nullptr, nullptr, nullptr, (bf16*)qpTH, (bf16*)qpTL, 0, BB * NQ, DD);
    // G2: kproj = key @ Wk^T + bk          (M=16384, N=256, K=256)
    gemm_kernel<1,256,0,0><<<dim3(1, 128, 1), 256, SM256>>>(
        (bf16*)kH, (bf16*)kL, 0, DD, (bf16*)wkH, (bf16*)wkL, 0, DD,
        bk, nullptr, nullptr, (bf16*)kpH, (bf16*)kpL, 0, DD, DD);

    // fold + row-1024 extraction (after G1)
    fold_kernel<<<(DD * BB * 1024 + 255) / 256, 256>>>();
    q1024_kernel<<<(BB * DD + 255) / 256, 256>>>();

    // G3: qfft = Cfold @ qpF^T + bq + (-1)^m q1024   (per b: M=1152, N=256, K=1024)
    gemm_kernel<1,128,1,0><<<dim3(2, 9, BB), 256, SM128>>>(
        (bf16*)CH, (bf16*)CL, 0, 1024, (bf16*)qpFH, (bf16*)qpFL, 1024, BB * 1024,
        bq, (const float*)q1024, nullptr, (bf16*)qfH, (bf16*)qfL,
        (size_t)MP * DD, DD, 1024);
    // G4: scores = qfft @ kproj^T          (per b: M=1152, N=2048, K=256)
    gemm_kernel<0,256,0,0><<<dim3(8, 9, BB), 256, SM256>>>(
        (bf16*)qfH, (bf16*)qfL, (size_t)MP * DD, DD,
        (bf16*)kpH, (bf16*)kpL, (size_t)NK * DD, DD,
        nullptr, nullptr, (float*)sc, nullptr, nullptr, (size_t)MP * NK, NK, DD);
    // softmax -> probs hi/lo
    softmax_kernel<<<BB * MP, 256>>>((float*)sc, (bf16*)pH, (bf16*)pL);
    // G5: partial out = probs @ vT^T, 2-way split-K  (per bz: M=1152, N=256, K=1024)
    gemm_kernel<0,128,0,1><<<dim3(2, 9, 16), 256, SM128>>>(
        (bf16*)pH, (bf16*)pL, (size_t)MP * NK, NK,
        (bf16*)vTH, (bf16*)vTL, (size_t)DD * NK, NK,
        nullptr, nullptr, (float*)op, nullptr, nullptr, (size_t)MP * DD, DD, 1024);
    // combine partials + mirror
    combine_kernel<<<dim3(1025, BB), 256>>>((const float*)op, out);
}